// round 2
// baseline (speedup 1.0000x reference)
#include <cuda_runtime.h>
#include <math.h>

#define BQ 2
#define HH 16
#define SS 2048
#define DK 64
#define DM 1024
#define MTOT (BQ*SS)   // 4096

// Scratch (allocation-free): per-head projections + concatenated context
__device__ float g_qh[BQ*HH*SS*DK];
__device__ float g_kh[BQ*HH*SS*DK];
__device__ float g_vh[BQ*HH*SS*DK];
__device__ float g_ctx[BQ*SS*DM];

// ---------------------------------------------------------------------------
// Projection GEMM: out[b,h,s,k] = sum_d X[b,s,d] * W[h,d,k]
// Block tile: 128 (M) x 64 (N = one head), BK = 16. 256 threads, 8x4 microtile.
// ---------------------------------------------------------------------------
__global__ __launch_bounds__(256) void proj_kernel(
    const float* __restrict__ X,      // [MTOT, DM]
    const float* __restrict__ W,      // [H, DM, DK]
    float* __restrict__ out)          // [B, H, S, DK]
{
    __shared__ float As[16][132];     // [kk][m], padded
    __shared__ float Bs[16][68];      // [kk][n], padded

    const int m0  = blockIdx.x * 128;
    const int h   = blockIdx.y;
    const int tid = threadIdx.x;
    const int tx  = tid & 15, ty = tid >> 4;

    const float* Wh = W + (size_t)h * DM * DK;

    float acc[8][4] = {};

    for (int k0 = 0; k0 < DM; k0 += 16) {
        // A tile: 128 rows x 16 cols -> transposed into As[kk][m]
        #pragma unroll
        for (int i = 0; i < 2; i++) {
            int f = tid * 2 + i;                 // 0..511 float4 slots
            int r = f >> 2, c4 = f & 3;
            float4 v = *reinterpret_cast<const float4*>(&X[(size_t)(m0 + r)*DM + k0 + c4*4]);
            As[c4*4+0][r] = v.x; As[c4*4+1][r] = v.y;
            As[c4*4+2][r] = v.z; As[c4*4+3][r] = v.w;
        }
        // B tile: 16 rows (d) x 64 cols (k) -- fully coalesced
        {
            int f = tid;                          // 0..255
            int d = f >> 4, c4 = f & 15;
            float4 v = *reinterpret_cast<const float4*>(&Wh[(size_t)(k0 + d)*DK + c4*4]);
            *reinterpret_cast<float4*>(&Bs[d][c4*4]) = v;
        }
        __syncthreads();

        #pragma unroll
        for (int kk = 0; kk < 16; kk++) {
            float a[8];
            #pragma unroll
            for (int i = 0; i < 8; i++) a[i] = As[kk][ty*8 + i];
            float4 bv = *reinterpret_cast<const float4*>(&Bs[kk][tx*4]);
            float b[4] = {bv.x, bv.y, bv.z, bv.w};
            #pragma unroll
            for (int i = 0; i < 8; i++)
                #pragma unroll
                for (int j = 0; j < 4; j++)
                    acc[i][j] = fmaf(a[i], b[j], acc[i][j]);
        }
        __syncthreads();
    }

    #pragma unroll
    for (int i = 0; i < 8; i++) {
        int m = m0 + ty*8 + i;
        int b = m >> 11, s = m & 2047;
        float4 v = {acc[i][0], acc[i][1], acc[i][2], acc[i][3]};
        *reinterpret_cast<float4*>(&out[((((size_t)b*HH + h)*SS + s))*DK + tx*4]) = v;
    }
}

// ---------------------------------------------------------------------------
// Flash attention: 64 q-rows per CTA, stream 64-key chunks.
// 256 threads (16x16), each owns a 4x4 tile of the 64x64 score/output tiles.
// ---------------------------------------------------------------------------
__global__ __launch_bounds__(256) void attn_kernel(
    const float* __restrict__ Q,      // [B,H,S,DK]
    const float* __restrict__ K,
    const float* __restrict__ V,
    float* __restrict__ ctx)          // [B,S,DM]
{
    extern __shared__ float sm[];
    float* Qs = sm;                   // 64 x 68
    float* Ks = Qs + 64*68;
    float* Vs = Ks + 64*68;
    float* Ps = Vs + 64*68;

    const int tid = threadIdx.x;
    const int tx  = tid & 15, ty = tid >> 4;
    const int q0  = blockIdx.x * 64;
    const int bh  = blockIdx.y;

    const float* Qb = Q + (size_t)bh * SS * DK;
    const float* Kb = K + (size_t)bh * SS * DK;
    const float* Vb = V + (size_t)bh * SS * DK;

    // Load Q tile once
    #pragma unroll
    for (int i = 0; i < 4; i++) {
        int f = i*256 + tid;          // 0..1023 float4 slots
        int r = f >> 4, c4 = f & 15;
        *reinterpret_cast<float4*>(&Qs[r*68 + c4*4]) =
            *reinterpret_cast<const float4*>(&Qb[(size_t)(q0 + r)*DK + c4*4]);
    }

    float O[4][4] = {};
    float mrow[4] = {-1e30f, -1e30f, -1e30f, -1e30f};
    float lrow[4] = {};

    for (int j0 = 0; j0 < SS; j0 += 64) {
        #pragma unroll
        for (int i = 0; i < 4; i++) {
            int f = i*256 + tid;
            int r = f >> 4, c4 = f & 15;
            *reinterpret_cast<float4*>(&Ks[r*68 + c4*4]) =
                *reinterpret_cast<const float4*>(&Kb[(size_t)(j0 + r)*DK + c4*4]);
            *reinterpret_cast<float4*>(&Vs[r*68 + c4*4]) =
                *reinterpret_cast<const float4*>(&Vb[(size_t)(j0 + r)*DK + c4*4]);
        }
        __syncthreads();

        // S = Q K^T for this 64x64 tile
        float s[4][4] = {};
        #pragma unroll
        for (int kk = 0; kk < 64; kk += 4) {
            float4 a[4], b[4];
            #pragma unroll
            for (int i = 0; i < 4; i++)
                a[i] = *reinterpret_cast<const float4*>(&Qs[(ty*4 + i)*68 + kk]);
            #pragma unroll
            for (int j = 0; j < 4; j++)
                b[j] = *reinterpret_cast<const float4*>(&Ks[(tx*4 + j)*68 + kk]);
            #pragma unroll
            for (int i = 0; i < 4; i++)
                #pragma unroll
                for (int j = 0; j < 4; j++)
                    s[i][j] += a[i].x*b[j].x + a[i].y*b[j].y
                             + a[i].z*b[j].z + a[i].w*b[j].w;
        }

        // Online softmax update (rows ty*4+i, reduce over the 16 tx threads)
        #pragma unroll
        for (int i = 0; i < 4; i++) {
            float rm = -1e30f;
            #pragma unroll
            for (int j = 0; j < 4; j++) { s[i][j] *= 0.125f; rm = fmaxf(rm, s[i][j]); }
            #pragma unroll
            for (int msk = 1; msk < 16; msk <<= 1)
                rm = fmaxf(rm, __shfl_xor_sync(0xffffffffu, rm, msk));
            float nm = fmaxf(mrow[i], rm);
            float alpha = __expf(mrow[i] - nm);
            float rs = 0.f;
            #pragma unroll
            for (int j = 0; j < 4; j++) { s[i][j] = __expf(s[i][j] - nm); rs += s[i][j]; }
            #pragma unroll
            for (int msk = 1; msk < 16; msk <<= 1)
                rs += __shfl_xor_sync(0xffffffffu, rs, msk);
            lrow[i] = lrow[i]*alpha + rs;
            mrow[i] = nm;
            #pragma unroll
            for (int j = 0; j < 4; j++) O[i][j] *= alpha;
        }

        // Stage P
        #pragma unroll
        for (int i = 0; i < 4; i++) {
            float4 v = {s[i][0], s[i][1], s[i][2], s[i][3]};
            *reinterpret_cast<float4*>(&Ps[(ty*4 + i)*68 + tx*4]) = v;
        }
        __syncthreads();

        // O += P @ V
        #pragma unroll
        for (int kk = 0; kk < 64; kk++) {
            float4 bv = *reinterpret_cast<const float4*>(&Vs[kk*68 + tx*4]);
            #pragma unroll
            for (int i = 0; i < 4; i++) {
                float p = Ps[(ty*4 + i)*68 + kk];
                O[i][0] = fmaf(p, bv.x, O[i][0]);
                O[i][1] = fmaf(p, bv.y, O[i][1]);
                O[i][2] = fmaf(p, bv.z, O[i][2]);
                O[i][3] = fmaf(p, bv.w, O[i][3]);
            }
        }
        __syncthreads();
    }

    // Epilogue: ctx[b, s, h*64 + k]
    const int b = bh >> 4, h = bh & 15;
    #pragma unroll
    for (int i = 0; i < 4; i++) {
        float inv = 1.0f / lrow[i];
        int srow = q0 + ty*4 + i;
        float4 v = {O[i][0]*inv, O[i][1]*inv, O[i][2]*inv, O[i][3]*inv};
        *reinterpret_cast<float4*>(&ctx[((size_t)b*SS + srow)*DM + h*DK + tx*4]) = v;
    }
}

// ---------------------------------------------------------------------------
// Output projection: out[m,n] = sum_k ctx[m,k] * Wo[n,k] + bo[n]
// ---------------------------------------------------------------------------
__global__ __launch_bounds__(256) void outproj_kernel(
    const float* __restrict__ X,      // [MTOT, DM]
    const float* __restrict__ Wo,     // [DM, DM] row = output feature
    const float* __restrict__ bo,     // [DM]
    float* __restrict__ out)          // [MTOT, DM]
{
    __shared__ float As[16][132];
    __shared__ float Bs[16][68];

    const int m0  = blockIdx.x * 128;
    const int n0  = blockIdx.y * 64;
    const int tid = threadIdx.x;
    const int tx  = tid & 15, ty = tid >> 4;

    float acc[8][4] = {};

    for (int k0 = 0; k0 < DM; k0 += 16) {
        #pragma unroll
        for (int i = 0; i < 2; i++) {
            int f = tid * 2 + i;
            int r = f >> 2, c4 = f & 3;
            float4 v = *reinterpret_cast<const float4*>(&X[(size_t)(m0 + r)*DM + k0 + c4*4]);
            As[c4*4+0][r] = v.x; As[c4*4+1][r] = v.y;
            As[c4*4+2][r] = v.z; As[c4*4+3][r] = v.w;
        }
        {
            int f = tid;
            int col = f >> 2, q4 = f & 3;     // B^T tile: Bs[kk][col] = Wo[n0+col][k0+kk]
            float4 v = *reinterpret_cast<const float4*>(&Wo[(size_t)(n0 + col)*DM + k0 + q4*4]);
            Bs[q4*4+0][col] = v.x; Bs[q4*4+1][col] = v.y;
            Bs[q4*4+2][col] = v.z; Bs[q4*4+3][col] = v.w;
        }
        __syncthreads();

        #pragma unroll
        for (int kk = 0; kk < 16; kk++) {
            float a[8];
            #pragma unroll
            for (int i = 0; i < 8; i++) a[i] = As[kk][ty*8 + i];
            float4 bv = *reinterpret_cast<const float4*>(&Bs[kk][tx*4]);
            float b[4] = {bv.x, bv.y, bv.z, bv.w};
            #pragma unroll
            for (int i = 0; i < 8; i++)
                #pragma unroll
                for (int j = 0; j < 4; j++)
                    acc[i][j] = fmaf(a[i], b[j], acc[i][j]);
        }
        __syncthreads();
    }

    float4 bias = *reinterpret_cast<const float4*>(&bo[n0 + tx*4]);
    #pragma unroll
    for (int i = 0; i < 8; i++) {
        int m = m0 + ty*8 + i;
        float4 v = {acc[i][0] + bias.x, acc[i][1] + bias.y,
                    acc[i][2] + bias.z, acc[i][3] + bias.w};
        *reinterpret_cast<float4*>(&out[(size_t)m*DM + n0 + tx*4]) = v;
    }
}

// ---------------------------------------------------------------------------
extern "C" void kernel_launch(void* const* d_in, const int* in_sizes, int n_in,
                              void* d_out, int out_size) {
    const float* q  = (const float*)d_in[0];
    const float* k  = (const float*)d_in[1];
    const float* v  = (const float*)d_in[2];
    const float* Wq = (const float*)d_in[3];
    const float* Wk = (const float*)d_in[4];
    const float* Wv = (const float*)d_in[5];
    const float* Wo = (const float*)d_in[6];
    const float* bo = (const float*)d_in[7];
    float* out = (float*)d_out;

    float *qh, *kh, *vh, *ctx;
    cudaGetSymbolAddress((void**)&qh,  g_qh);
    cudaGetSymbolAddress((void**)&kh,  g_kh);
    cudaGetSymbolAddress((void**)&vh,  g_vh);
    cudaGetSymbolAddress((void**)&ctx, g_ctx);

    const int attn_smem = 4 * 64 * 68 * (int)sizeof(float);   // 69632 B
    cudaFuncSetAttribute(attn_kernel, cudaFuncAttributeMaxDynamicSharedMemorySize, attn_smem);

    dim3 gproj(MTOT/128, HH);
    proj_kernel<<<gproj, 256>>>(q, Wq, qh);
    proj_kernel<<<gproj, 256>>>(k, Wk, kh);
    proj_kernel<<<gproj, 256>>>(v, Wv, vh);

    attn_kernel<<<dim3(SS/64, BQ*HH), 256, attn_smem>>>(qh, kh, vh, ctx);

    outproj_kernel<<<dim3(MTOT/128, DM/64), 256>>>(ctx, Wo, bo, out);
}

// round 3
// speedup vs baseline: 3.4737x; 3.4737x over previous
#include <cuda_runtime.h>
#include <math.h>
#include <stdint.h>

#define BQ 2
#define HH 16
#define SS 2048
#define DK 64
#define DM 1024
#define MTOT (BQ*SS)   // 4096

// Scratch (allocation-free)
__device__ float g_qh[BQ*HH*SS*DK];
__device__ float g_kh[BQ*HH*SS*DK];
__device__ float g_vh[BQ*HH*SS*DK];
__device__ float g_ctx[BQ*SS*DM];

// ---------------------------------------------------------------------------
// tf32 helpers
// ---------------------------------------------------------------------------
__device__ __forceinline__ uint32_t f2tf(float x) {
    uint32_t u;
    asm("cvt.rna.tf32.f32 %0, %1;" : "=r"(u) : "f"(x));
    return u;
}

// D += A(16x8) * B(8x8), tf32 inputs, fp32 accumulate
__device__ __forceinline__ void mma8(float4& d,
                                     uint32_t a0, uint32_t a1, uint32_t a2, uint32_t a3,
                                     uint32_t b0, uint32_t b1) {
    asm volatile(
        "mma.sync.aligned.m16n8k8.row.col.f32.tf32.tf32.f32 "
        "{%0,%1,%2,%3},{%4,%5,%6,%7},{%8,%9},{%0,%1,%2,%3};"
        : "+f"(d.x), "+f"(d.y), "+f"(d.z), "+f"(d.w)
        : "r"(a0), "r"(a1), "r"(a2), "r"(a3), "r"(b0), "r"(b1));
}

// ---------------------------------------------------------------------------
// Projection GEMM (tf32 mma): out[b,h,s,k] = sum_d X[b,s,d] * W[h,d,k]
// CTA tile 128(M) x 64(N=head). 8 warps: 4(m) x 2(n), warp tile 32x32.
// ---------------------------------------------------------------------------
__global__ __launch_bounds__(256) void proj_tf32(
    const float* __restrict__ X,      // [MTOT, DM]
    const float* __restrict__ W,      // [H, DM, DK]
    float* __restrict__ out)          // [B, H, S, DK]
{
    __shared__ uint32_t As[128*36];   // [m][k], pad 36 -> conflict-free frag loads
    __shared__ uint32_t Bs[32*72];    // [k][n], pad 72 -> conflict-free frag loads

    const int tid = threadIdx.x, lane = tid & 31, warp = tid >> 5;
    const int gid = lane >> 2, tig = lane & 3;
    const int wm = (warp >> 1) * 32, wn = (warp & 1) * 32;
    const int m0 = blockIdx.x * 128, h = blockIdx.y;
    const float* Wh = W + (size_t)h * DM * DK;

    float4 acc[2][4];
    #pragma unroll
    for (int i = 0; i < 2; i++)
        #pragma unroll
        for (int j = 0; j < 4; j++) acc[i][j] = make_float4(0.f, 0.f, 0.f, 0.f);

    for (int k0 = 0; k0 < DM; k0 += 32) {
        #pragma unroll
        for (int i = 0; i < 4; i++) {                 // A: 128x32 = 1024 float4
            int f = tid + i*256;
            int r = f >> 3, c4 = f & 7;
            float4 v = *reinterpret_cast<const float4*>(&X[(size_t)(m0 + r)*DM + k0 + c4*4]);
            uint4 t = make_uint4(f2tf(v.x), f2tf(v.y), f2tf(v.z), f2tf(v.w));
            *reinterpret_cast<uint4*>(&As[r*36 + c4*4]) = t;
        }
        #pragma unroll
        for (int i = 0; i < 2; i++) {                 // B: 32x64 = 512 float4
            int f = tid + i*256;
            int r = f >> 4, c4 = f & 15;
            float4 v = *reinterpret_cast<const float4*>(&Wh[(size_t)(k0 + r)*DK + c4*4]);
            uint4 t = make_uint4(f2tf(v.x), f2tf(v.y), f2tf(v.z), f2tf(v.w));
            *reinterpret_cast<uint4*>(&Bs[r*72 + c4*4]) = t;
        }
        __syncthreads();

        #pragma unroll
        for (int kk = 0; kk < 32; kk += 8) {
            uint32_t b0[4], b1[4];
            #pragma unroll
            for (int j = 0; j < 4; j++) {
                b0[j] = Bs[(kk + tig)*72   + wn + j*8 + gid];
                b1[j] = Bs[(kk + tig + 4)*72 + wn + j*8 + gid];
            }
            #pragma unroll
            for (int i = 0; i < 2; i++) {
                int ra = (wm + i*16 + gid)*36 + kk + tig;
                uint32_t a0 = As[ra],          a2 = As[ra + 4];
                uint32_t a1 = As[ra + 8*36],   a3 = As[ra + 8*36 + 4];
                #pragma unroll
                for (int j = 0; j < 4; j++) mma8(acc[i][j], a0, a1, a2, a3, b0[j], b1[j]);
            }
        }
        __syncthreads();
    }

    #pragma unroll
    for (int i = 0; i < 2; i++) {
        int r0 = m0 + wm + i*16 + gid, r1 = r0 + 8;
        float* o0 = &out[(((size_t)(r0 >> 11)*HH + h)*SS + (r0 & 2047))*DK];
        float* o1 = &out[(((size_t)(r1 >> 11)*HH + h)*SS + (r1 & 2047))*DK];
        #pragma unroll
        for (int j = 0; j < 4; j++) {
            int c = wn + j*8 + tig*2;
            *reinterpret_cast<float2*>(&o0[c]) = make_float2(acc[i][j].x, acc[i][j].y);
            *reinterpret_cast<float2*>(&o1[c]) = make_float2(acc[i][j].z, acc[i][j].w);
        }
    }
}

// ---------------------------------------------------------------------------
// Flash attention (tf32 mma): 128 q-rows per CTA, 64-key chunks.
// 8 warps; warp w owns score/output rows [w*16, w*16+16) x all 64 cols.
// ---------------------------------------------------------------------------
__global__ __launch_bounds__(256) void attn_tf32(
    const float* __restrict__ Q,      // [B,H,S,DK]
    const float* __restrict__ K,
    const float* __restrict__ V,
    float* __restrict__ ctx)          // [B,S,DM]
{
    extern __shared__ uint32_t sm4[];
    uint32_t* Qs = sm4;               // 128 x 68
    uint32_t* Ks = Qs + 128*68;       // 64 x 68   ([key][dk])
    uint32_t* Vs = Ks + 64*68;        // 64 x 72   ([key][dk])
    uint32_t* Ps = Vs + 64*72;        // 128 x 68

    const int tid = threadIdx.x, lane = tid & 31, warp = tid >> 5;
    const int gid = lane >> 2, tig = lane & 3;
    const int wr = warp * 16;
    const int q0 = blockIdx.x * 128;
    const int bh = blockIdx.y;

    const float* Qb = Q + (size_t)bh * SS * DK;
    const float* Kb = K + (size_t)bh * SS * DK;
    const float* Vb = V + (size_t)bh * SS * DK;

    // Stage Q once, pre-scaled by 1/sqrt(dk)=0.125
    #pragma unroll
    for (int i = 0; i < 8; i++) {
        int f = tid + i*256;           // 128x16 float4
        int r = f >> 4, c4 = f & 15;
        float4 v = *reinterpret_cast<const float4*>(&Qb[(size_t)(q0 + r)*DK + c4*4]);
        uint4 t = make_uint4(f2tf(v.x*0.125f), f2tf(v.y*0.125f),
                             f2tf(v.z*0.125f), f2tf(v.w*0.125f));
        *reinterpret_cast<uint4*>(&Qs[r*68 + c4*4]) = t;
    }

    float4 o[8];
    #pragma unroll
    for (int j = 0; j < 8; j++) o[j] = make_float4(0.f, 0.f, 0.f, 0.f);
    float m0r = -1e30f, m1r = -1e30f, l0 = 0.f, l1 = 0.f;

    for (int j0 = 0; j0 < SS; j0 += 64) {
        #pragma unroll
        for (int i = 0; i < 4; i++) {  // K,V: 64x16 float4 each
            int f = tid + i*256;
            int r = f >> 4, c4 = f & 15;
            float4 kv = *reinterpret_cast<const float4*>(&Kb[(size_t)(j0 + r)*DK + c4*4]);
            *reinterpret_cast<uint4*>(&Ks[r*68 + c4*4]) =
                make_uint4(f2tf(kv.x), f2tf(kv.y), f2tf(kv.z), f2tf(kv.w));
            float4 vv = *reinterpret_cast<const float4*>(&Vb[(size_t)(j0 + r)*DK + c4*4]);
            *reinterpret_cast<uint4*>(&Vs[r*72 + c4*4]) =
                make_uint4(f2tf(vv.x), f2tf(vv.y), f2tf(vv.z), f2tf(vv.w));
        }
        __syncthreads();

        // S = Q K^T (scores already scaled via Q)
        float4 s[8];
        #pragma unroll
        for (int j = 0; j < 8; j++) s[j] = make_float4(0.f, 0.f, 0.f, 0.f);
        #pragma unroll
        for (int kk = 0; kk < 64; kk += 8) {
            int ra = (wr + gid)*68 + kk + tig;
            uint32_t a0 = Qs[ra],        a2 = Qs[ra + 4];
            uint32_t a1 = Qs[ra + 8*68], a3 = Qs[ra + 8*68 + 4];
            #pragma unroll
            for (int j = 0; j < 8; j++) {
                int rb = (j*8 + gid)*68 + kk + tig;
                mma8(s[j], a0, a1, a2, a3, Ks[rb], Ks[rb + 4]);
            }
        }

        // Online softmax (rows r0=wr+gid, r1=wr+gid+8; reduce over tig lanes)
        float mx0 = -1e30f, mx1 = -1e30f;
        #pragma unroll
        for (int j = 0; j < 8; j++) {
            mx0 = fmaxf(mx0, fmaxf(s[j].x, s[j].y));
            mx1 = fmaxf(mx1, fmaxf(s[j].z, s[j].w));
        }
        mx0 = fmaxf(mx0, __shfl_xor_sync(0xffffffffu, mx0, 1));
        mx0 = fmaxf(mx0, __shfl_xor_sync(0xffffffffu, mx0, 2));
        mx1 = fmaxf(mx1, __shfl_xor_sync(0xffffffffu, mx1, 1));
        mx1 = fmaxf(mx1, __shfl_xor_sync(0xffffffffu, mx1, 2));
        float nm0 = fmaxf(m0r, mx0), nm1 = fmaxf(m1r, mx1);
        float al0 = __expf(m0r - nm0), al1 = __expf(m1r - nm1);
        float rs0 = 0.f, rs1 = 0.f;
        #pragma unroll
        for (int j = 0; j < 8; j++) {
            s[j].x = __expf(s[j].x - nm0);
            s[j].y = __expf(s[j].y - nm0);
            s[j].z = __expf(s[j].z - nm1);
            s[j].w = __expf(s[j].w - nm1);
            rs0 += s[j].x + s[j].y;
            rs1 += s[j].z + s[j].w;
        }
        rs0 += __shfl_xor_sync(0xffffffffu, rs0, 1);
        rs0 += __shfl_xor_sync(0xffffffffu, rs0, 2);
        rs1 += __shfl_xor_sync(0xffffffffu, rs1, 1);
        rs1 += __shfl_xor_sync(0xffffffffu, rs1, 2);
        l0 = l0*al0 + rs0;  l1 = l1*al1 + rs1;
        m0r = nm0;          m1r = nm1;
        #pragma unroll
        for (int j = 0; j < 8; j++) {
            o[j].x *= al0; o[j].y *= al0; o[j].z *= al1; o[j].w *= al1;
        }

        // Stage P (warp-private rows)
        #pragma unroll
        for (int j = 0; j < 8; j++) {
            int c = j*8 + tig*2;
            *reinterpret_cast<uint2*>(&Ps[(wr + gid)*68 + c]) =
                make_uint2(f2tf(s[j].x), f2tf(s[j].y));
            *reinterpret_cast<uint2*>(&Ps[(wr + gid + 8)*68 + c]) =
                make_uint2(f2tf(s[j].z), f2tf(s[j].w));
        }
        __syncwarp();

        // O += P @ V
        #pragma unroll
        for (int kk = 0; kk < 64; kk += 8) {
            int ra = (wr + gid)*68 + kk + tig;
            uint32_t a0 = Ps[ra],        a2 = Ps[ra + 4];
            uint32_t a1 = Ps[ra + 8*68], a3 = Ps[ra + 8*68 + 4];
            #pragma unroll
            for (int j = 0; j < 8; j++) {
                int rb = (kk + tig)*72 + j*8 + gid;
                mma8(o[j], a0, a1, a2, a3, Vs[rb], Vs[rb + 4*72]);
            }
        }
        __syncthreads();
    }

    // Epilogue: ctx[b, s, h*64 + c]
    const int b = bh >> 4, h = bh & 15;
    const float inv0 = 1.f / l0, inv1 = 1.f / l1;
    const int r0 = q0 + wr + gid, r1 = r0 + 8;
    float* c0 = &ctx[((size_t)b*SS + r0)*DM + h*DK];
    float* c1 = &ctx[((size_t)b*SS + r1)*DM + h*DK];
    #pragma unroll
    for (int j = 0; j < 8; j++) {
        int c = j*8 + tig*2;
        *reinterpret_cast<float2*>(&c0[c]) = make_float2(o[j].x*inv0, o[j].y*inv0);
        *reinterpret_cast<float2*>(&c1[c]) = make_float2(o[j].z*inv1, o[j].w*inv1);
    }
}

// ---------------------------------------------------------------------------
// Output projection (tf32 mma): out[m,n] = sum_k ctx[m,k]*Wo[n,k] + bo[n]
// ---------------------------------------------------------------------------
__global__ __launch_bounds__(256) void outproj_tf32(
    const float* __restrict__ X,      // [MTOT, DM]
    const float* __restrict__ Wo,     // [DM, DM], row n = output feature
    const float* __restrict__ bo,     // [DM]
    float* __restrict__ out)          // [MTOT, DM]
{
    __shared__ uint32_t As[128*36];
    __shared__ uint32_t Bs[32*72];    // [k][n]

    const int tid = threadIdx.x, lane = tid & 31, warp = tid >> 5;
    const int gid = lane >> 2, tig = lane & 3;
    const int wm = (warp >> 1) * 32, wn = (warp & 1) * 32;
    const int m0 = blockIdx.x * 128, n0 = blockIdx.y * 64;

    float4 acc[2][4];
    #pragma unroll
    for (int i = 0; i < 2; i++)
        #pragma unroll
        for (int j = 0; j < 4; j++) acc[i][j] = make_float4(0.f, 0.f, 0.f, 0.f);

    for (int k0 = 0; k0 < DM; k0 += 32) {
        #pragma unroll
        for (int i = 0; i < 4; i++) {
            int f = tid + i*256;
            int r = f >> 3, c4 = f & 7;
            float4 v = *reinterpret_cast<const float4*>(&X[(size_t)(m0 + r)*DM + k0 + c4*4]);
            uint4 t = make_uint4(f2tf(v.x), f2tf(v.y), f2tf(v.z), f2tf(v.w));
            *reinterpret_cast<uint4*>(&As[r*36 + c4*4]) = t;
        }
        // B: transpose Wo rows [n0, n0+64) x k chunk into Bs[k][n]
        #pragma unroll
        for (int i = 0; i < 2; i++) {
            int f = tid + i*256;
            int r = f >> 3, c4 = f & 7;     // r: 0..63 (n), c4: 0..7 (k/4)
            float4 v = *reinterpret_cast<const float4*>(&Wo[(size_t)(n0 + r)*DM + k0 + c4*4]);
            Bs[(c4*4 + 0)*72 + r] = f2tf(v.x);
            Bs[(c4*4 + 1)*72 + r] = f2tf(v.y);
            Bs[(c4*4 + 2)*72 + r] = f2tf(v.z);
            Bs[(c4*4 + 3)*72 + r] = f2tf(v.w);
        }
        __syncthreads();

        #pragma unroll
        for (int kk = 0; kk < 32; kk += 8) {
            uint32_t b0[4], b1[4];
            #pragma unroll
            for (int j = 0; j < 4; j++) {
                b0[j] = Bs[(kk + tig)*72   + wn + j*8 + gid];
                b1[j] = Bs[(kk + tig + 4)*72 + wn + j*8 + gid];
            }
            #pragma unroll
            for (int i = 0; i < 2; i++) {
                int ra = (wm + i*16 + gid)*36 + kk + tig;
                uint32_t a0 = As[ra],        a2 = As[ra + 4];
                uint32_t a1 = As[ra + 8*36], a3 = As[ra + 8*36 + 4];
                #pragma unroll
                for (int j = 0; j < 4; j++) mma8(acc[i][j], a0, a1, a2, a3, b0[j], b1[j]);
            }
        }
        __syncthreads();
    }

    #pragma unroll
    for (int i = 0; i < 2; i++) {
        int r0 = m0 + wm + i*16 + gid, r1 = r0 + 8;
        #pragma unroll
        for (int j = 0; j < 4; j++) {
            int c = n0 + wn + j*8 + tig*2;
            float bx = bo[c], by = bo[c + 1];
            *reinterpret_cast<float2*>(&out[(size_t)r0*DM + c]) =
                make_float2(acc[i][j].x + bx, acc[i][j].y + by);
            *reinterpret_cast<float2*>(&out[(size_t)r1*DM + c]) =
                make_float2(acc[i][j].z + bx, acc[i][j].w + by);
        }
    }
}

// ---------------------------------------------------------------------------
extern "C" void kernel_launch(void* const* d_in, const int* in_sizes, int n_in,
                              void* d_out, int out_size) {
    const float* q  = (const float*)d_in[0];
    const float* k  = (const float*)d_in[1];
    const float* v  = (const float*)d_in[2];
    const float* Wq = (const float*)d_in[3];
    const float* Wk = (const float*)d_in[4];
    const float* Wv = (const float*)d_in[5];
    const float* Wo = (const float*)d_in[6];
    const float* bo = (const float*)d_in[7];
    float* out = (float*)d_out;

    float *qh, *kh, *vh, *ctx;
    cudaGetSymbolAddress((void**)&qh,  g_qh);
    cudaGetSymbolAddress((void**)&kh,  g_kh);
    cudaGetSymbolAddress((void**)&vh,  g_vh);
    cudaGetSymbolAddress((void**)&ctx, g_ctx);

    const int attn_smem = (128*68 + 64*68 + 64*72 + 128*68) * (int)sizeof(uint32_t); // 105472
    cudaFuncSetAttribute(attn_tf32, cudaFuncAttributeMaxDynamicSharedMemorySize, attn_smem);

    dim3 gproj(MTOT/128, HH);
    proj_tf32<<<gproj, 256>>>(q, Wq, qh);
    proj_tf32<<<gproj, 256>>>(k, Wk, kh);
    proj_tf32<<<gproj, 256>>>(v, Wv, vh);

    attn_tf32<<<dim3(SS/128, BQ*HH), 256, attn_smem>>>(qh, kh, vh, ctx);

    outproj_tf32<<<dim3(MTOT/128, DM/64), 256>>>(ctx, Wo, bo, out);
}

// round 4
// speedup vs baseline: 4.6300x; 1.3329x over previous
#include <cuda_runtime.h>
#include <math.h>
#include <stdint.h>

#define BQ 2
#define HH 16
#define SS 2048
#define DK 64
#define DM 1024
#define MTOT (BQ*SS)   // 4096

__device__ float g_qh[BQ*HH*SS*DK];
__device__ float g_kh[BQ*HH*SS*DK];
__device__ float g_vh[BQ*HH*SS*DK];
__device__ float g_ctx[BQ*SS*DM];

// ---------------------------------------------------------------------------
__device__ __forceinline__ uint32_t f2tf(float x) {
    uint32_t u;
    asm("cvt.rna.tf32.f32 %0, %1;" : "=r"(u) : "f"(x));
    return u;
}

__device__ __forceinline__ void mma8(float4& d,
                                     uint32_t a0, uint32_t a1, uint32_t a2, uint32_t a3,
                                     uint32_t b0, uint32_t b1) {
    asm volatile(
        "mma.sync.aligned.m16n8k8.row.col.f32.tf32.tf32.f32 "
        "{%0,%1,%2,%3},{%4,%5,%6,%7},{%8,%9},{%0,%1,%2,%3};"
        : "+f"(d.x), "+f"(d.y), "+f"(d.z), "+f"(d.w)
        : "r"(a0), "r"(a1), "r"(a2), "r"(a3), "r"(b0), "r"(b1));
}

__device__ __forceinline__ void cp16(float* sdst, const float* gsrc) {
    uint32_t sa = (uint32_t)__cvta_generic_to_shared(sdst);
    asm volatile("cp.async.cg.shared.global [%0], [%1], 16;" :: "r"(sa), "l"(gsrc) : "memory");
}
#define CP_COMMIT() asm volatile("cp.async.commit_group;" ::: "memory")
#define CP_WAIT1()  asm volatile("cp.async.wait_group 1;" ::: "memory")

// ---------------------------------------------------------------------------
// Fused QKV projection GEMM: out_z[b,h,s,k] = sum_d X_z[b,s,d] * W_z[h,d,k]
// CTA 128x128, BK=32, cp.async double-buffered. 8 warps (2m x 4n), warp 64x32.
// grid: (MTOT/128, 1024/128, 3)
// ---------------------------------------------------------------------------
#define A_STRIDE 36
#define B_STRIDE 136
#define A_TILE (128*A_STRIDE)
#define B_TILE (32*B_STRIDE)

__global__ __launch_bounds__(256) void proj_gemm(
    const float* __restrict__ Xq, const float* __restrict__ Xk, const float* __restrict__ Xv,
    const float* __restrict__ Wq, const float* __restrict__ Wk, const float* __restrict__ Wv,
    float* __restrict__ Oq, float* __restrict__ Ok, float* __restrict__ Ov)
{
    extern __shared__ float sm[];
    float* As = sm;                    // 2 x [128][36]
    float* Bs = sm + 2*A_TILE;         // 2 x [32][136]  ([k][n])

    const int z = blockIdx.z;
    const float* X = (z == 0) ? Xq : (z == 1) ? Xk : Xv;
    const float* W = (z == 0) ? Wq : (z == 1) ? Wk : Wv;
    float* out     = (z == 0) ? Oq : (z == 1) ? Ok : Ov;

    const int tid = threadIdx.x, lane = tid & 31, warp = tid >> 5;
    const int gid = lane >> 2, tig = lane & 3;
    const int wm = (warp >> 2) * 64, wn = (warp & 3) * 32;
    const int m0 = blockIdx.x * 128, n0 = blockIdx.y * 128;

    float4 acc[4][4];
    #pragma unroll
    for (int i = 0; i < 4; i++)
        #pragma unroll
        for (int j = 0; j < 4; j++) acc[i][j] = make_float4(0.f, 0.f, 0.f, 0.f);

    auto stage = [&](int buf, int k0) {
        float* Ab = As + buf*A_TILE;
        float* Bb = Bs + buf*B_TILE;
        #pragma unroll
        for (int i = 0; i < 4; i++) {               // A: 128x32 fp32
            int f = tid + i*256;
            int r = f >> 3, c = f & 7;
            cp16(&Ab[r*A_STRIDE + c*4], &X[(size_t)(m0 + r)*DM + k0 + c*4]);
        }
        #pragma unroll
        for (int i = 0; i < 4; i++) {               // B: 32x128 fp32, head-indexed
            int f = tid + i*256;
            int r = f >> 5, c = f & 31;
            int n = n0 + c*4;
            int h = n >> 6, kc = n & 63;
            cp16(&Bb[r*B_STRIDE + c*4], &W[((size_t)h*DM + k0 + r)*DK + kc]);
        }
    };

    stage(0, 0);  CP_COMMIT();
    stage(1, 32); CP_COMMIT();

    #pragma unroll 1
    for (int k0 = 0; k0 < DM; k0 += 32) {
        int buf = (k0 >> 5) & 1;
        CP_WAIT1();
        __syncthreads();
        const float* Ab = As + buf*A_TILE;
        const float* Bb = Bs + buf*B_TILE;

        #pragma unroll
        for (int kk = 0; kk < 32; kk += 8) {
            uint32_t a[4][4];
            #pragma unroll
            for (int i = 0; i < 4; i++) {
                int ra = (wm + i*16 + gid)*A_STRIDE + kk + tig;
                a[i][0] = f2tf(Ab[ra]);
                a[i][1] = f2tf(Ab[ra + 8*A_STRIDE]);
                a[i][2] = f2tf(Ab[ra + 4]);
                a[i][3] = f2tf(Ab[ra + 8*A_STRIDE + 4]);
            }
            uint32_t b[4][2];
            #pragma unroll
            for (int j = 0; j < 4; j++) {
                int rb = (kk + tig)*B_STRIDE + wn + j*8 + gid;
                b[j][0] = f2tf(Bb[rb]);
                b[j][1] = f2tf(Bb[rb + 4*B_STRIDE]);
            }
            #pragma unroll
            for (int i = 0; i < 4; i++)
                #pragma unroll
                for (int j = 0; j < 4; j++)
                    mma8(acc[i][j], a[i][0], a[i][1], a[i][2], a[i][3], b[j][0], b[j][1]);
        }
        __syncthreads();
        if (k0 + 64 < DM) stage(buf, k0 + 64);
        CP_COMMIT();
    }

    // Epilogue: out[b, h, s, k]
    #pragma unroll
    for (int i = 0; i < 4; i++) {
        int r0 = m0 + wm + i*16 + gid, r1 = r0 + 8;
        int b0i = r0 >> 11, s0 = r0 & 2047;
        int b1i = r1 >> 11, s1 = r1 & 2047;
        #pragma unroll
        for (int j = 0; j < 4; j++) {
            int c = n0 + wn + j*8 + tig*2;
            int h = c >> 6, kc = c & 63;
            *reinterpret_cast<float2*>(&out[(((size_t)b0i*HH + h)*SS + s0)*DK + kc]) =
                make_float2(acc[i][j].x, acc[i][j].y);
            *reinterpret_cast<float2*>(&out[(((size_t)b1i*HH + h)*SS + s1)*DK + kc]) =
                make_float2(acc[i][j].z, acc[i][j].w);
        }
    }
}

// ---------------------------------------------------------------------------
// Output projection GEMM: out[m,n] = sum_k ctx[m,k]*Wo[n,k] + bo[n]
// Same pipeline; B staged transposed as [n][k].
// ---------------------------------------------------------------------------
__global__ __launch_bounds__(256) void outproj_gemm(
    const float* __restrict__ X, const float* __restrict__ Wo,
    const float* __restrict__ bo, float* __restrict__ out)
{
    extern __shared__ float sm[];
    float* As = sm;                    // 2 x [128][36]
    float* Bt = sm + 2*A_TILE;         // 2 x [128][36]  ([n][k])

    const int tid = threadIdx.x, lane = tid & 31, warp = tid >> 5;
    const int gid = lane >> 2, tig = lane & 3;
    const int wm = (warp >> 2) * 64, wn = (warp & 3) * 32;
    const int m0 = blockIdx.x * 128, n0 = blockIdx.y * 128;

    float4 acc[4][4];
    #pragma unroll
    for (int i = 0; i < 4; i++)
        #pragma unroll
        for (int j = 0; j < 4; j++) acc[i][j] = make_float4(0.f, 0.f, 0.f, 0.f);

    auto stage = [&](int buf, int k0) {
        float* Ab = As + buf*A_TILE;
        float* Bb = Bt + buf*A_TILE;
        #pragma unroll
        for (int i = 0; i < 4; i++) {
            int f = tid + i*256;
            int r = f >> 3, c = f & 7;
            cp16(&Ab[r*A_STRIDE + c*4], &X[(size_t)(m0 + r)*DM + k0 + c*4]);
            cp16(&Bb[r*A_STRIDE + c*4], &Wo[(size_t)(n0 + r)*DM + k0 + c*4]);
        }
    };

    stage(0, 0);  CP_COMMIT();
    stage(1, 32); CP_COMMIT();

    #pragma unroll 1
    for (int k0 = 0; k0 < DM; k0 += 32) {
        int buf = (k0 >> 5) & 1;
        CP_WAIT1();
        __syncthreads();
        const float* Ab = As + buf*A_TILE;
        const float* Bb = Bt + buf*A_TILE;

        #pragma unroll
        for (int kk = 0; kk < 32; kk += 8) {
            uint32_t a[4][4];
            #pragma unroll
            for (int i = 0; i < 4; i++) {
                int ra = (wm + i*16 + gid)*A_STRIDE + kk + tig;
                a[i][0] = f2tf(Ab[ra]);
                a[i][1] = f2tf(Ab[ra + 8*A_STRIDE]);
                a[i][2] = f2tf(Ab[ra + 4]);
                a[i][3] = f2tf(Ab[ra + 8*A_STRIDE + 4]);
            }
            uint32_t b[4][2];
            #pragma unroll
            for (int j = 0; j < 4; j++) {
                int rb = (wn + j*8 + gid)*A_STRIDE + kk + tig;
                b[j][0] = f2tf(Bb[rb]);
                b[j][1] = f2tf(Bb[rb + 4]);
            }
            #pragma unroll
            for (int i = 0; i < 4; i++)
                #pragma unroll
                for (int j = 0; j < 4; j++)
                    mma8(acc[i][j], a[i][0], a[i][1], a[i][2], a[i][3], b[j][0], b[j][1]);
        }
        __syncthreads();
        if (k0 + 64 < DM) stage(buf, k0 + 64);
        CP_COMMIT();
    }

    #pragma unroll
    for (int i = 0; i < 4; i++) {
        int r0 = m0 + wm + i*16 + gid, r1 = r0 + 8;
        #pragma unroll
        for (int j = 0; j < 4; j++) {
            int c = n0 + wn + j*8 + tig*2;
            float bx = bo[c], by = bo[c + 1];
            *reinterpret_cast<float2*>(&out[(size_t)r0*DM + c]) =
                make_float2(acc[i][j].x + bx, acc[i][j].y + by);
            *reinterpret_cast<float2*>(&out[(size_t)r1*DM + c]) =
                make_float2(acc[i][j].z + bx, acc[i][j].w + by);
        }
    }
}

// ---------------------------------------------------------------------------
// Flash attention v3: Q fragments in registers, P via register shuffle.
// 128 q-rows/CTA, 64-key chunks, 8 warps (warp = 16 q-rows).
// ---------------------------------------------------------------------------
__global__ __launch_bounds__(256) void attn3(
    const float* __restrict__ Q, const float* __restrict__ K,
    const float* __restrict__ V, float* __restrict__ ctx)
{
    __shared__ uint32_t sbuf[64*68 + 64*72];     // 35840 B
    uint32_t* Ks = sbuf;            // [key][dk]  64 x 68
    uint32_t* Vs = sbuf + 64*68;    // [key][dk]  64 x 72

    const int tid = threadIdx.x, lane = tid & 31, warp = tid >> 5;
    const int gid = lane >> 2, tig = lane & 3;
    const int wr = warp * 16;
    const int q0 = blockIdx.x * 128;
    const int bh = blockIdx.y;
    const unsigned FULL = 0xffffffffu;

    const float* Qb = Q + (size_t)bh * SS * DK;
    const float* Kb = K + (size_t)bh * SS * DK;
    const float* Vb = V + (size_t)bh * SS * DK;

    // Stage Q (scaled by 1/8, tf32) into sbuf flat [128][68], then lift to regs
    #pragma unroll
    for (int i = 0; i < 8; i++) {
        int f = tid + i*256;
        int r = f >> 4, c4 = f & 15;
        float4 v = *reinterpret_cast<const float4*>(&Qb[(size_t)(q0 + r)*DK + c4*4]);
        uint4 t = make_uint4(f2tf(v.x*0.125f), f2tf(v.y*0.125f),
                             f2tf(v.z*0.125f), f2tf(v.w*0.125f));
        *reinterpret_cast<uint4*>(&sbuf[r*68 + c4*4]) = t;
    }
    __syncthreads();
    uint32_t q[8][4];
    #pragma unroll
    for (int t = 0; t < 8; t++) {
        int ra = (wr + gid)*68 + t*8 + tig;
        q[t][0] = sbuf[ra];
        q[t][1] = sbuf[ra + 8*68];
        q[t][2] = sbuf[ra + 4];
        q[t][3] = sbuf[ra + 8*68 + 4];
    }
    __syncthreads();

    float4 o[8];
    #pragma unroll
    for (int j = 0; j < 8; j++) o[j] = make_float4(0.f, 0.f, 0.f, 0.f);
    float m0r = -1e30f, m1r = -1e30f, l0 = 0.f, l1 = 0.f;

    const int sl0 = (lane & 28) | (tig >> 1);
    const bool odd = (tig & 1);

    for (int j0 = 0; j0 < SS; j0 += 64) {
        #pragma unroll
        for (int i = 0; i < 4; i++) {     // stage K,V chunk (64x16 float4 each)
            int f = tid + i*256;
            int r = f >> 4, c4 = f & 15;
            float4 kv = *reinterpret_cast<const float4*>(&Kb[(size_t)(j0 + r)*DK + c4*4]);
            *reinterpret_cast<uint4*>(&Ks[r*68 + c4*4]) =
                make_uint4(f2tf(kv.x), f2tf(kv.y), f2tf(kv.z), f2tf(kv.w));
            float4 vv = *reinterpret_cast<const float4*>(&Vb[(size_t)(j0 + r)*DK + c4*4]);
            *reinterpret_cast<uint4*>(&Vs[r*72 + c4*4]) =
                make_uint4(f2tf(vv.x), f2tf(vv.y), f2tf(vv.z), f2tf(vv.w));
        }
        __syncthreads();

        // S = Q K^T (Q pre-scaled)
        float4 s[8];
        #pragma unroll
        for (int j = 0; j < 8; j++) s[j] = make_float4(0.f, 0.f, 0.f, 0.f);
        #pragma unroll
        for (int t = 0; t < 8; t++) {
            #pragma unroll
            for (int j = 0; j < 8; j++) {
                int rb = (j*8 + gid)*68 + t*8 + tig;
                mma8(s[j], q[t][0], q[t][1], q[t][2], q[t][3], Ks[rb], Ks[rb + 4]);
            }
        }

        // Online softmax
        float mx0 = -1e30f, mx1 = -1e30f;
        #pragma unroll
        for (int j = 0; j < 8; j++) {
            mx0 = fmaxf(mx0, fmaxf(s[j].x, s[j].y));
            mx1 = fmaxf(mx1, fmaxf(s[j].z, s[j].w));
        }
        mx0 = fmaxf(mx0, __shfl_xor_sync(FULL, mx0, 1));
        mx0 = fmaxf(mx0, __shfl_xor_sync(FULL, mx0, 2));
        mx1 = fmaxf(mx1, __shfl_xor_sync(FULL, mx1, 1));
        mx1 = fmaxf(mx1, __shfl_xor_sync(FULL, mx1, 2));
        float nm0 = fmaxf(m0r, mx0), nm1 = fmaxf(m1r, mx1);
        float al0 = __expf(m0r - nm0), al1 = __expf(m1r - nm1);
        float rs0 = 0.f, rs1 = 0.f;
        #pragma unroll
        for (int j = 0; j < 8; j++) {
            s[j].x = __expf(s[j].x - nm0);
            s[j].y = __expf(s[j].y - nm0);
            s[j].z = __expf(s[j].z - nm1);
            s[j].w = __expf(s[j].w - nm1);
            rs0 += s[j].x + s[j].y;
            rs1 += s[j].z + s[j].w;
        }
        rs0 += __shfl_xor_sync(FULL, rs0, 1);
        rs0 += __shfl_xor_sync(FULL, rs0, 2);
        rs1 += __shfl_xor_sync(FULL, rs1, 1);
        rs1 += __shfl_xor_sync(FULL, rs1, 2);
        l0 = l0*al0 + rs0;  l1 = l1*al1 + rs1;
        m0r = nm0;          m1r = nm1;
        #pragma unroll
        for (int j = 0; j < 8; j++) {
            o[j].x *= al0; o[j].y *= al0; o[j].z *= al1; o[j].w *= al1;
        }

        // O += P @ V : convert S-accum block j -> A fragments via shuffle
        #pragma unroll
        for (int j = 0; j < 8; j++) {
            float x0 = __shfl_sync(FULL, s[j].x, sl0);
            float y0 = __shfl_sync(FULL, s[j].y, sl0);
            float z0 = __shfl_sync(FULL, s[j].z, sl0);
            float w0 = __shfl_sync(FULL, s[j].w, sl0);
            float x1 = __shfl_sync(FULL, s[j].x, sl0 + 2);
            float y1 = __shfl_sync(FULL, s[j].y, sl0 + 2);
            float z1 = __shfl_sync(FULL, s[j].z, sl0 + 2);
            float w1 = __shfl_sync(FULL, s[j].w, sl0 + 2);
            uint32_t a0 = f2tf(odd ? y0 : x0);
            uint32_t a1 = f2tf(odd ? w0 : z0);
            uint32_t a2 = f2tf(odd ? y1 : x1);
            uint32_t a3 = f2tf(odd ? w1 : z1);
            #pragma unroll
            for (int jn = 0; jn < 8; jn++) {
                int rb = (j*8 + tig)*72 + jn*8 + gid;
                mma8(o[jn], a0, a1, a2, a3, Vs[rb], Vs[rb + 4*72]);
            }
        }
        __syncthreads();
    }

    // Epilogue: ctx[b, s, h*64 + c]
    const int b = bh >> 4, h = bh & 15;
    const float inv0 = 1.f / l0, inv1 = 1.f / l1;
    const int r0 = q0 + wr + gid, r1 = r0 + 8;
    float* c0 = &ctx[((size_t)b*SS + r0)*DM + h*DK];
    float* c1 = &ctx[((size_t)b*SS + r1)*DM + h*DK];
    #pragma unroll
    for (int j = 0; j < 8; j++) {
        int c = j*8 + tig*2;
        *reinterpret_cast<float2*>(&c0[c]) = make_float2(o[j].x*inv0, o[j].y*inv0);
        *reinterpret_cast<float2*>(&c1[c]) = make_float2(o[j].z*inv1, o[j].w*inv1);
    }
}

// ---------------------------------------------------------------------------
extern "C" void kernel_launch(void* const* d_in, const int* in_sizes, int n_in,
                              void* d_out, int out_size) {
    const float* q  = (const float*)d_in[0];
    const float* k  = (const float*)d_in[1];
    const float* v  = (const float*)d_in[2];
    const float* Wq = (const float*)d_in[3];
    const float* Wk = (const float*)d_in[4];
    const float* Wv = (const float*)d_in[5];
    const float* Wo = (const float*)d_in[6];
    const float* bo = (const float*)d_in[7];
    float* out = (float*)d_out;

    float *qh, *kh, *vh, *ctx;
    cudaGetSymbolAddress((void**)&qh,  g_qh);
    cudaGetSymbolAddress((void**)&kh,  g_kh);
    cudaGetSymbolAddress((void**)&vh,  g_vh);
    cudaGetSymbolAddress((void**)&ctx, g_ctx);

    const int proj_smem = (2*A_TILE + 2*B_TILE) * (int)sizeof(float);   // 71680
    const int outp_smem = (4*A_TILE) * (int)sizeof(float);              // 73728
    cudaFuncSetAttribute(proj_gemm,    cudaFuncAttributeMaxDynamicSharedMemorySize, proj_smem);
    cudaFuncSetAttribute(outproj_gemm, cudaFuncAttributeMaxDynamicSharedMemorySize, outp_smem);

    proj_gemm<<<dim3(MTOT/128, DM/128, 3), 256, proj_smem>>>(
        q, k, v, Wq, Wk, Wv, qh, kh, vh);

    attn3<<<dim3(SS/128, BQ*HH), 256>>>(qh, kh, vh, ctx);

    outproj_gemm<<<dim3(MTOT/128, DM/128), 256, outp_smem>>>(ctx, Wo, bo, out);
}